// round 16
// baseline (speedup 1.0000x reference)
#include <cuda_runtime.h>
#include <cuda_fp16.h>

#define NUM_USERS 100000
#define NUM_ITEMS 100000
#define N_NODES   200000
#define EMB       64
#define N_EDGES   3200000
#define SCAN_CHUNK 1024
#define NB ((N_NODES + SCAN_CHUNK - 1) / SCAN_CHUNK)   // 196

// ---------------- scratch (no allocations allowed) ----------------
// g_cnt is zero at module load and k_scan23 re-zeroes it after use, so every
// call (correctness, capture, every replay) sees zeroed counters.
__device__ int  g_cnt[N_NODES];
__device__ int  g_off[N_NODES];
__device__ int  g_cur[N_NODES];
__device__ int  g_bsum[NB];
__device__ __align__(16) int2   g_edge[N_EDGES];               // {col, w-bits} sorted by row
__device__ __align__(16) __half g_h0[(size_t)N_NODES * EMB];   // ego0
__device__ __align__(16) __half g_h1[(size_t)N_NODES * EMB];   // ego1
__device__ __align__(16) __half g_h2[(size_t)N_NODES * EMB];   // ego2

// -------- init + histogram fused (g_cnt guaranteed zero on entry) ---------
__global__ void k_init_hist(const float* __restrict__ user,
                            const float* __restrict__ item,
                            const int* __restrict__ edge_row) {
    int i = blockIdx.x * blockDim.x + threadIdx.x;
    int stride = gridDim.x * blockDim.x;
    const int NV4 = (N_NODES * EMB) / 4;
    const int UV4 = (NUM_USERS * EMB) / 4;
    const float4* u4 = reinterpret_cast<const float4*>(user);
    const float4* t4 = reinterpret_cast<const float4*>(item);
    uint2* h4 = reinterpret_cast<uint2*>(g_h0);
    for (int j = i; j < NV4; j += stride) {
        float4 f = (j < UV4) ? u4[j] : t4[j - UV4];
        __half2 a = __floats2half2_rn(f.x, f.y);
        __half2 b = __floats2half2_rn(f.z, f.w);
        uint2 p;
        p.x = *reinterpret_cast<unsigned*>(&a);
        p.y = *reinterpret_cast<unsigned*>(&b);
        h4[j] = p;
    }
    for (int e = i; e < N_EDGES; e += stride)
        atomicAdd(&g_cnt[__ldg(&edge_row[e])], 1);
}

// ---------------- scan stage 1: per-chunk inclusive scan ------------------
__global__ void k_scan1() {
    __shared__ int s[SCAN_CHUNK];
    int tid = threadIdx.x;
    int gid = blockIdx.x * SCAN_CHUNK + tid;
    int v = (gid < N_NODES) ? g_cnt[gid] : 0;
    s[tid] = v;
    __syncthreads();
    for (int d = 1; d < SCAN_CHUNK; d <<= 1) {
        int t = (tid >= d) ? s[tid - d] : 0;
        __syncthreads();
        s[tid] += t;
        __syncthreads();
    }
    if (gid < N_NODES) g_off[gid] = s[tid];
    if (tid == SCAN_CHUNK - 1) g_bsum[blockIdx.x] = s[tid];
}

// ---------------- scan stage 2+3 fused + g_cnt reset ----------------------
__global__ void k_scan23() {
    __shared__ int s[256];
    int tid = threadIdx.x;
    s[tid] = (tid < NB) ? g_bsum[tid] : 0;
    __syncthreads();
    for (int d = 1; d < 256; d <<= 1) {
        int t = (tid >= d) ? s[tid - d] : 0;
        __syncthreads();
        s[tid] += t;
        __syncthreads();
    }
    int i = blockIdx.x * blockDim.x + tid;
    if (i < N_NODES) {
        int chunk = i / SCAN_CHUNK;
        int bpre = (chunk == 0) ? 0 : s[chunk - 1];
        int excl = g_off[i] - g_cnt[i] + bpre;
        g_off[i] = excl;
        g_cur[i] = excl;
        g_cnt[i] = 0;              // restore invariant for next replay
    }
}

// ---------------- scatter edges into CSR order (proven R7 version) -------
__global__ void k_scatter(const int* __restrict__ edge_row,
                          const int* __restrict__ edge_col,
                          const float* __restrict__ edge_w) {
    int e = blockIdx.x * blockDim.x + threadIdx.x;
    if (e < N_EDGES) {
        int r = __ldg(&edge_row[e]);
        int pos = atomicAdd(&g_cur[r], 1);
        int2 packed;
        packed.x = __ldg(&edge_col[e]);
        packed.y = __float_as_int(__ldg(&edge_w[e]));
        g_edge[pos] = packed;
    }
}

// ------- warp-collective CSR SpMM: staged edges, front-batched gathers ----
// One warp per row. Per 32-edge chunk: ONE coalesced LDG.64 loads the whole
// edge segment (lane l -> edge base+l); indices/weights distributed via shfl
// (register-only). The 8 batch-gathers (4 edges each: g=lane>>3 picks the
// edge, s=lane&7 picks the 16B slice of its 128B row) have NO memory
// dependence on each other -> fully unrolled, 8 LDG.128 in flight per warp.
// Lanes past the row end hold {0,0}: they gather row 0 (L1-hot, ~free) with
// weight bits 0 == 0.0f, so no masking in the loop.
// MODE 0: x=g_h0 -> y=g_h1
// MODE 1: x=g_h1 -> y=g_h2
// MODE 2: x=g_h2;  out = (h1 + h2 + acc)/3
template <int MODE>
__global__ __launch_bounds__(256) void k_spmm(float* __restrict__ out) {
    int warp = (blockIdx.x * blockDim.x + threadIdx.x) >> 5;
    int lane = threadIdx.x & 31;
    if (warp >= N_NODES) return;
    int g = lane >> 3;
    int s = lane & 7;

    int start = g_off[warp];
    int end   = (warp == N_NODES - 1) ? N_EDGES : g_off[warp + 1];

    const __half* xp = (MODE == 0) ? g_h0 : (MODE == 1) ? g_h1 : g_h2;
    const uint4* __restrict__ x4 = reinterpret_cast<const uint4*>(xp);

    float acc[8];
#pragma unroll
    for (int j = 0; j < 8; j++) acc[j] = 0.f;

    for (int base = start; base < end; base += 32) {
        // stage this chunk's edges: one coalesced 8B load per lane
        int2 ed;
        ed.x = 0; ed.y = 0;                       // col 0, weight +0.0f
        if (base + lane < end)
            ed = __ldg(&g_edge[base + lane]);

        // 8 independent gathers, all issued before any is consumed
        uint4 hv[8];
        float w[8];
#pragma unroll
        for (int b = 0; b < 8; b++) {
            int src = b * 4 + g;                  // lane holding edge base+src
            int c     = __shfl_sync(0xFFFFFFFF, ed.x, src);
            int wbits = __shfl_sync(0xFFFFFFFF, ed.y, src);
            w[b] = __int_as_float(wbits);
            hv[b] = __ldg(&x4[(size_t)c * 8 + s]);
        }

#pragma unroll
        for (int b = 0; b < 8; b++) {
            float2 f0 = __half22float2(*reinterpret_cast<__half2*>(&hv[b].x));
            float2 f1 = __half22float2(*reinterpret_cast<__half2*>(&hv[b].y));
            float2 f2 = __half22float2(*reinterpret_cast<__half2*>(&hv[b].z));
            float2 f3 = __half22float2(*reinterpret_cast<__half2*>(&hv[b].w));
            acc[0] = fmaf(w[b], f0.x, acc[0]);
            acc[1] = fmaf(w[b], f0.y, acc[1]);
            acc[2] = fmaf(w[b], f1.x, acc[2]);
            acc[3] = fmaf(w[b], f1.y, acc[3]);
            acc[4] = fmaf(w[b], f2.x, acc[4]);
            acc[5] = fmaf(w[b], f2.y, acc[5]);
            acc[6] = fmaf(w[b], f3.x, acc[6]);
            acc[7] = fmaf(w[b], f3.y, acc[7]);
        }
    }

    // reduce across the 4 edge groups (lane bits 3,4)
#pragma unroll
    for (int j = 0; j < 8; j++) {
        acc[j] += __shfl_xor_sync(0xFFFFFFFF, acc[j], 8);
        acc[j] += __shfl_xor_sync(0xFFFFFFFF, acc[j], 16);
    }

    if (g == 0) {
        int ridx = warp * 8 + s;                 // uint4 index of this 16B chunk
        if (MODE != 2) {
            __half2 y0 = __floats2half2_rn(acc[0], acc[1]);
            __half2 y1 = __floats2half2_rn(acc[2], acc[3]);
            __half2 y2 = __floats2half2_rn(acc[4], acc[5]);
            __half2 y3 = __floats2half2_rn(acc[6], acc[7]);
            uint4 pk;
            pk.x = *reinterpret_cast<unsigned*>(&y0);
            pk.y = *reinterpret_cast<unsigned*>(&y1);
            pk.z = *reinterpret_cast<unsigned*>(&y2);
            pk.w = *reinterpret_cast<unsigned*>(&y3);
            uint4* yp = reinterpret_cast<uint4*>((MODE == 0) ? g_h1 : g_h2);
            yp[ridx] = pk;
        } else {
            // out = (ego1 + ego2 + ego3) / 3
            uint4 a1 = __ldg(&reinterpret_cast<const uint4*>(g_h1)[ridx]);
            uint4 a2 = __ldg(&reinterpret_cast<const uint4*>(g_h2)[ridx]);
            const float sc = 1.0f / 3.0f;
            float4 o0, o1;
            float2 t;
            t = __half22float2(*reinterpret_cast<__half2*>(&a1.x));
            o0.x = t.x; o0.y = t.y;
            t = __half22float2(*reinterpret_cast<__half2*>(&a1.y));
            o0.z = t.x; o0.w = t.y;
            t = __half22float2(*reinterpret_cast<__half2*>(&a1.z));
            o1.x = t.x; o1.y = t.y;
            t = __half22float2(*reinterpret_cast<__half2*>(&a1.w));
            o1.z = t.x; o1.w = t.y;
            t = __half22float2(*reinterpret_cast<__half2*>(&a2.x));
            o0.x += t.x; o0.y += t.y;
            t = __half22float2(*reinterpret_cast<__half2*>(&a2.y));
            o0.z += t.x; o0.w += t.y;
            t = __half22float2(*reinterpret_cast<__half2*>(&a2.z));
            o1.x += t.x; o1.y += t.y;
            t = __half22float2(*reinterpret_cast<__half2*>(&a2.w));
            o1.z += t.x; o1.w += t.y;
            o0.x = (o0.x + acc[0]) * sc; o0.y = (o0.y + acc[1]) * sc;
            o0.z = (o0.z + acc[2]) * sc; o0.w = (o0.w + acc[3]) * sc;
            o1.x = (o1.x + acc[4]) * sc; o1.y = (o1.y + acc[5]) * sc;
            o1.z = (o1.z + acc[6]) * sc; o1.w = (o1.w + acc[7]) * sc;
            float4* out4 = reinterpret_cast<float4*>(out);
            out4[2 * ridx]     = o0;
            out4[2 * ridx + 1] = o1;
        }
    }
}

// ---------------- launch ----------------
extern "C" void kernel_launch(void* const* d_in, const int* in_sizes, int n_in,
                              void* d_out, int out_size) {
    const float* user_emb = (const float*)d_in[0];
    const float* item_emb = (const float*)d_in[1];
    const float* edge_w   = (const float*)d_in[2];
    const int*   edge_row = (const int*)d_in[3];
    const int*   edge_col = (const int*)d_in[4];
    float* out = (float*)d_out;

    k_init_hist<<<2048, 256>>>(user_emb, item_emb, edge_row);
    k_scan1<<<NB, SCAN_CHUNK>>>();
    k_scan23<<<(N_NODES + 255) / 256, 256>>>();
    k_scatter<<<(N_EDGES + 255) / 256, 256>>>(edge_row, edge_col, edge_w);

    const int SPMM_BLOCKS = (N_NODES * 32 + 255) / 256;   // one warp per row
    k_spmm<0><<<SPMM_BLOCKS, 256>>>(out);
    k_spmm<1><<<SPMM_BLOCKS, 256>>>(out);
    k_spmm<2><<<SPMM_BLOCKS, 256>>>(out);
}

// round 17
// speedup vs baseline: 1.3372x; 1.3372x over previous
#include <cuda_runtime.h>
#include <cuda_fp16.h>

#define NUM_USERS 100000
#define NUM_ITEMS 100000
#define N_NODES   200000
#define EMB       64
#define N_EDGES   3200000
#define SCAN_CHUNK 1024
#define NB ((N_NODES + SCAN_CHUNK - 1) / SCAN_CHUNK)   // 196
#define ROWS_PER_WARP 4

// ---------------- scratch (no allocations allowed) ----------------
// g_cnt is zero at module load and k_scan23 re-zeroes it after use, so every
// call (correctness, capture, every replay) sees zeroed counters.
__device__ int  g_cnt[N_NODES];
__device__ int  g_off[N_NODES];
__device__ int  g_cur[N_NODES];
__device__ int  g_bsum[NB];
__device__ __align__(16) int2   g_edge[N_EDGES];               // {col, w-bits} sorted by row
__device__ __align__(16) __half g_h0[(size_t)N_NODES * EMB];   // ego0
__device__ __align__(16) __half g_h1[(size_t)N_NODES * EMB];   // ego1
__device__ __align__(16) __half g_h2[(size_t)N_NODES * EMB];   // ego2

// -------- init + histogram fused (g_cnt guaranteed zero on entry) ---------
__global__ void k_init_hist(const float* __restrict__ user,
                            const float* __restrict__ item,
                            const int* __restrict__ edge_row) {
    int i = blockIdx.x * blockDim.x + threadIdx.x;
    int stride = gridDim.x * blockDim.x;
    const int NV4 = (N_NODES * EMB) / 4;
    const int UV4 = (NUM_USERS * EMB) / 4;
    const float4* u4 = reinterpret_cast<const float4*>(user);
    const float4* t4 = reinterpret_cast<const float4*>(item);
    uint2* h4 = reinterpret_cast<uint2*>(g_h0);
    for (int j = i; j < NV4; j += stride) {
        float4 f = (j < UV4) ? u4[j] : t4[j - UV4];
        __half2 a = __floats2half2_rn(f.x, f.y);
        __half2 b = __floats2half2_rn(f.z, f.w);
        uint2 p;
        p.x = *reinterpret_cast<unsigned*>(&a);
        p.y = *reinterpret_cast<unsigned*>(&b);
        h4[j] = p;
    }
    for (int e = i; e < N_EDGES; e += stride)
        atomicAdd(&g_cnt[__ldg(&edge_row[e])], 1);
}

// ---------------- scan stage 1: per-chunk inclusive scan ------------------
__global__ void k_scan1() {
    __shared__ int s[SCAN_CHUNK];
    int tid = threadIdx.x;
    int gid = blockIdx.x * SCAN_CHUNK + tid;
    int v = (gid < N_NODES) ? g_cnt[gid] : 0;
    s[tid] = v;
    __syncthreads();
    for (int d = 1; d < SCAN_CHUNK; d <<= 1) {
        int t = (tid >= d) ? s[tid - d] : 0;
        __syncthreads();
        s[tid] += t;
        __syncthreads();
    }
    if (gid < N_NODES) g_off[gid] = s[tid];
    if (tid == SCAN_CHUNK - 1) g_bsum[blockIdx.x] = s[tid];
}

// ---------------- scan stage 2+3 fused + g_cnt reset ----------------------
__global__ void k_scan23() {
    __shared__ int s[256];
    int tid = threadIdx.x;
    s[tid] = (tid < NB) ? g_bsum[tid] : 0;
    __syncthreads();
    for (int d = 1; d < 256; d <<= 1) {
        int t = (tid >= d) ? s[tid - d] : 0;
        __syncthreads();
        s[tid] += t;
        __syncthreads();
    }
    int i = blockIdx.x * blockDim.x + tid;
    if (i < N_NODES) {
        int chunk = i / SCAN_CHUNK;
        int bpre = (chunk == 0) ? 0 : s[chunk - 1];
        int excl = g_off[i] - g_cnt[i] + bpre;
        g_off[i] = excl;
        g_cur[i] = excl;
        g_cnt[i] = 0;              // restore invariant for next replay
    }
}

// ---------------- scatter edges into CSR order (proven R7 version) -------
__global__ void k_scatter(const int* __restrict__ edge_row,
                          const int* __restrict__ edge_col,
                          const float* __restrict__ edge_w) {
    int e = blockIdx.x * blockDim.x + threadIdx.x;
    if (e < N_EDGES) {
        int r = __ldg(&edge_row[e]);
        int pos = atomicAdd(&g_cur[r], 1);
        int2 packed;
        packed.x = __ldg(&edge_col[e]);
        packed.y = __float_as_int(__ldg(&edge_w[e]));
        g_edge[pos] = packed;
    }
}

// ------- CSR SpMM: proven R7 inner loop, 4 rows per warp -----------------
// Inner loop identical to the 274.6us kernel (4 edges/iter, one-batch-ahead
// edge prefetch). Each warp processes ROWS_PER_WARP consecutive rows to
// amortize per-row prologue/epilogue and block-scheduling cost (grid 4x
// smaller). g = lane>>3 (edge group), s = lane&7 (16B chunk of 128B row).
// MODE 0: x=g_h0 -> y=g_h1
// MODE 1: x=g_h1 -> y=g_h2
// MODE 2: x=g_h2;  out = (h1 + h2 + acc)/3
template <int MODE>
__global__ __launch_bounds__(256) void k_spmm(float* __restrict__ out) {
    int warp0 = (blockIdx.x * blockDim.x + threadIdx.x) >> 5;
    int lane = threadIdx.x & 31;
    int g = lane >> 3;
    int s = lane & 7;

    const __half* xp = (MODE == 0) ? g_h0 : (MODE == 1) ? g_h1 : g_h2;
    const uint4* __restrict__ x4 = reinterpret_cast<const uint4*>(xp);

    int row0 = warp0 * ROWS_PER_WARP;

#pragma unroll 1
    for (int r = 0; r < ROWS_PER_WARP; r++) {
        int row = row0 + r;
        if (row >= N_NODES) return;

        int start = g_off[row];
        int end   = (row == N_NODES - 1) ? N_EDGES : g_off[row + 1];

        float acc[8];
#pragma unroll
        for (int j = 0; j < 8; j++) acc[j] = 0.f;

        if (start < end) {
            // prime the pipeline (identical to 274.6us kernel)
            bool v = (start + g) < end;
            int2 ed = __ldg(&g_edge[v ? (start + g) : (end - 1)]);

            for (int e = start; e < end; e += 4) {
                int2 cur = ed;
                float w = v ? __int_as_float(cur.y) : 0.f;
                int ne = e + 4;
                if (ne < end) {                     // prefetch next batch
                    v = (ne + g) < end;
                    ed = __ldg(&g_edge[v ? (ne + g) : (end - 1)]);
                }
                uint4 hv = __ldg(&x4[(size_t)cur.x * 8 + s]);
                __half2 p0 = *reinterpret_cast<__half2*>(&hv.x);
                __half2 p1 = *reinterpret_cast<__half2*>(&hv.y);
                __half2 p2 = *reinterpret_cast<__half2*>(&hv.z);
                __half2 p3 = *reinterpret_cast<__half2*>(&hv.w);
                float2 f0 = __half22float2(p0);
                float2 f1 = __half22float2(p1);
                float2 f2 = __half22float2(p2);
                float2 f3 = __half22float2(p3);
                acc[0] = fmaf(w, f0.x, acc[0]);
                acc[1] = fmaf(w, f0.y, acc[1]);
                acc[2] = fmaf(w, f1.x, acc[2]);
                acc[3] = fmaf(w, f1.y, acc[3]);
                acc[4] = fmaf(w, f2.x, acc[4]);
                acc[5] = fmaf(w, f2.y, acc[5]);
                acc[6] = fmaf(w, f3.x, acc[6]);
                acc[7] = fmaf(w, f3.y, acc[7]);
            }
        }

        // reduce across the 4 edge groups
#pragma unroll
        for (int j = 0; j < 8; j++) {
            acc[j] += __shfl_xor_sync(0xFFFFFFFF, acc[j], 8);
            acc[j] += __shfl_xor_sync(0xFFFFFFFF, acc[j], 16);
        }

        if (g == 0) {
            int ridx = row * 8 + s;              // uint4 index of this 16B chunk
            if (MODE != 2) {
                __half2 y0 = __floats2half2_rn(acc[0], acc[1]);
                __half2 y1 = __floats2half2_rn(acc[2], acc[3]);
                __half2 y2 = __floats2half2_rn(acc[4], acc[5]);
                __half2 y3 = __floats2half2_rn(acc[6], acc[7]);
                uint4 pk;
                pk.x = *reinterpret_cast<unsigned*>(&y0);
                pk.y = *reinterpret_cast<unsigned*>(&y1);
                pk.z = *reinterpret_cast<unsigned*>(&y2);
                pk.w = *reinterpret_cast<unsigned*>(&y3);
                uint4* yp = reinterpret_cast<uint4*>((MODE == 0) ? g_h1 : g_h2);
                yp[ridx] = pk;
            } else {
                // out = (ego1 + ego2 + ego3) / 3
                uint4 a1 = __ldg(&reinterpret_cast<const uint4*>(g_h1)[ridx]);
                uint4 a2 = __ldg(&reinterpret_cast<const uint4*>(g_h2)[ridx]);
                const float sc = 1.0f / 3.0f;
                float4 o0, o1;
                float2 t;
                t = __half22float2(*reinterpret_cast<__half2*>(&a1.x));
                o0.x = t.x; o0.y = t.y;
                t = __half22float2(*reinterpret_cast<__half2*>(&a1.y));
                o0.z = t.x; o0.w = t.y;
                t = __half22float2(*reinterpret_cast<__half2*>(&a1.z));
                o1.x = t.x; o1.y = t.y;
                t = __half22float2(*reinterpret_cast<__half2*>(&a1.w));
                o1.z = t.x; o1.w = t.y;
                t = __half22float2(*reinterpret_cast<__half2*>(&a2.x));
                o0.x += t.x; o0.y += t.y;
                t = __half22float2(*reinterpret_cast<__half2*>(&a2.y));
                o0.z += t.x; o0.w += t.y;
                t = __half22float2(*reinterpret_cast<__half2*>(&a2.z));
                o1.x += t.x; o1.y += t.y;
                t = __half22float2(*reinterpret_cast<__half2*>(&a2.w));
                o1.z += t.x; o1.w += t.y;
                o0.x = (o0.x + acc[0]) * sc; o0.y = (o0.y + acc[1]) * sc;
                o0.z = (o0.z + acc[2]) * sc; o0.w = (o0.w + acc[3]) * sc;
                o1.x = (o1.x + acc[4]) * sc; o1.y = (o1.y + acc[5]) * sc;
                o1.z = (o1.z + acc[6]) * sc; o1.w = (o1.w + acc[7]) * sc;
                float4* out4 = reinterpret_cast<float4*>(out);
                out4[2 * ridx]     = o0;
                out4[2 * ridx + 1] = o1;
            }
        }
    }
}

// ---------------- launch ----------------
extern "C" void kernel_launch(void* const* d_in, const int* in_sizes, int n_in,
                              void* d_out, int out_size) {
    const float* user_emb = (const float*)d_in[0];
    const float* item_emb = (const float*)d_in[1];
    const float* edge_w   = (const float*)d_in[2];
    const int*   edge_row = (const int*)d_in[3];
    const int*   edge_col = (const int*)d_in[4];
    float* out = (float*)d_out;

    k_init_hist<<<2048, 256>>>(user_emb, item_emb, edge_row);
    k_scan1<<<NB, SCAN_CHUNK>>>();
    k_scan23<<<(N_NODES + 255) / 256, 256>>>();
    k_scatter<<<(N_EDGES + 255) / 256, 256>>>(edge_row, edge_col, edge_w);

    // 8 warps/block, ROWS_PER_WARP rows per warp
    const int WARPS_NEEDED = (N_NODES + ROWS_PER_WARP - 1) / ROWS_PER_WARP;
    const int SPMM_BLOCKS = (WARPS_NEEDED + 7) / 8;
    k_spmm<0><<<SPMM_BLOCKS, 256>>>(out);
    k_spmm<1><<<SPMM_BLOCKS, 256>>>(out);
    k_spmm<2><<<SPMM_BLOCKS, 256>>>(out);
}